// round 1
// baseline (speedup 1.0000x reference)
#include <cuda_runtime.h>
#include <math.h>

#define NHEAD 16
#define HS    64
#define CEMB  1024
#define BB    4
#define TT    2048
#define MTOT  (BB*TT)          // 8192

// Scratch (module-load allocated; not a runtime alloc)
__device__ float g_q[(size_t)BB*NHEAD*TT*HS];
__device__ float g_k[(size_t)BB*NHEAD*TT*HS];
__device__ float g_v[(size_t)BB*NHEAD*TT*HS];
__device__ float g_att[(size_t)MTOT*CEMB];

// ---------------------------------------------------------------------------
// SGEMM 128x128x8, 256 threads, 8x8 per thread.
// mode z: 0=Q(+RoPE), 1=K(+RoPE), 2=V  -> writes [B,H,T,D] scratch
// ---------------------------------------------------------------------------
__global__ void __launch_bounds__(256) qkv_gemm(
    const float* __restrict__ X,
    const float* __restrict__ Wq,
    const float* __restrict__ Wk,
    const float* __restrict__ Wv)
{
    const int mode = blockIdx.z;
    const float* W = (mode == 0) ? Wq : ((mode == 1) ? Wk : Wv);
    float* dst = (mode == 0) ? g_q : ((mode == 1) ? g_k : g_v);

    __shared__ float As[8][128];
    __shared__ float Bs[8][128];

    const int tid = threadIdx.x;
    const int tx = tid & 15;
    const int ty = tid >> 4;
    const int m0 = blockIdx.y * 128;
    const int n0 = blockIdx.x * 128;

    float acc[8][8];
#pragma unroll
    for (int i = 0; i < 8; i++)
#pragma unroll
        for (int j = 0; j < 8; j++) acc[i][j] = 0.0f;

    const int a_row = tid >> 1;         // 0..127
    const int a_col = (tid & 1) * 4;    // 0 or 4
    const int b_row = tid >> 5;         // 0..7
    const int b_col = (tid & 31) * 4;   // 0..124

    const float* Aptr = X + (size_t)(m0 + a_row) * CEMB + a_col;
    const float* Bptr = W + (size_t)b_row * CEMB + n0 + b_col;

    for (int kb = 0; kb < CEMB; kb += 8) {
        float4 av = *(const float4*)(Aptr + kb);
        As[a_col + 0][a_row] = av.x;
        As[a_col + 1][a_row] = av.y;
        As[a_col + 2][a_row] = av.z;
        As[a_col + 3][a_row] = av.w;
        float4 bv = *(const float4*)(Bptr + (size_t)kb * CEMB);
        *(float4*)&Bs[b_row][b_col] = bv;
        __syncthreads();
#pragma unroll
        for (int k = 0; k < 8; k++) {
            float4 a0 = *(const float4*)&As[k][ty * 8];
            float4 a1 = *(const float4*)&As[k][ty * 8 + 4];
            float4 b0 = *(const float4*)&Bs[k][tx * 8];
            float4 b1 = *(const float4*)&Bs[k][tx * 8 + 4];
            float ar[8] = {a0.x, a0.y, a0.z, a0.w, a1.x, a1.y, a1.z, a1.w};
            float br[8] = {b0.x, b0.y, b0.z, b0.w, b1.x, b1.y, b1.z, b1.w};
#pragma unroll
            for (int i = 0; i < 8; i++)
#pragma unroll
                for (int j = 0; j < 8; j++)
                    acc[i][j] += ar[i] * br[j];
        }
        __syncthreads();
    }

    // Epilogue: RoPE on q/k pairs, scatter to [B,H,T,D]
    const float L2T = 13.287712379549449f / 64.0f;  // log2(10000)/64
#pragma unroll
    for (int i = 0; i < 8; i++) {
        const int r = m0 + ty * 8 + i;
        const int b = r >> 11;       // / 2048
        const int t = r & 2047;
#pragma unroll
        for (int jp = 0; jp < 4; jp++) {
            const int n = n0 + tx * 8 + 2 * jp;
            const int h = n >> 6;
            const int d = n & 63;
            float x0 = acc[i][2 * jp];
            float x1 = acc[i][2 * jp + 1];
            float o0 = x0, o1 = x1;
            if (mode < 2) {
                const int p = d >> 1;
                float inv = exp2f(-(float)(2 * p) * L2T);
                float ang = (float)t * inv;
                float sv, cv;
                sincosf(ang, &sv, &cv);
                o0 = x0 * cv - x1 * sv;
                o1 = x0 * sv + x1 * cv;
            }
            size_t base = ((size_t)(b * NHEAD + h) * TT + t) * HS + d;
            dst[base]     = o0;
            dst[base + 1] = o1;
        }
    }
}

// ---------------------------------------------------------------------------
// Flash attention fp32, causal. One thread per query row. BM=128, BN=64.
// Shared: Qst[64][129] (d-major, scaled), Kt[64][68] (d-major),
//         Vs[64][68] (j-major), Ps[128][65] (per-row probs, dynamic index).
// ---------------------------------------------------------------------------
#define FL_QST (64 * 129)
#define FL_KT  (64 * 68)
#define FL_VS  (64 * 68)
#define FL_PS  (128 * 65)
#define FL_SMEM_FLOATS (FL_QST + FL_KT + FL_VS + FL_PS)
#define FL_SMEM_BYTES  (FL_SMEM_FLOATS * 4)

__global__ void __launch_bounds__(128) flash_kernel()
{
    extern __shared__ float sm[];
    float* Qst = sm;
    float* Kt  = Qst + FL_QST;
    float* Vs  = Kt + FL_KT;
    float* Ps  = Vs + FL_VS;

    const int tid = threadIdx.x;
    const int q0  = blockIdx.x * 128;
    const int bh  = blockIdx.y;

    const float* Q = g_q + (size_t)bh * TT * HS;
    const float* K = g_k + (size_t)bh * TT * HS;
    const float* V = g_v + (size_t)bh * TT * HS;

    // Load Q tile (scaled by 1/sqrt(64)=0.125), transposed d-major
    for (int it = 0; it < 64; ++it) {
        int idx = it * 128 + tid;
        int r = idx >> 6, d = idx & 63;
        Qst[d * 129 + r] = Q[(size_t)(q0 + r) * HS + d] * 0.125f;
    }

    float4 o4[16];
#pragma unroll
    for (int i = 0; i < 16; i++) o4[i] = make_float4(0.f, 0.f, 0.f, 0.f);
    float m = -1e30f, l = 0.f;

    const int qrow = q0 + tid;
    const int nkt = (q0 >> 6) + 2;

    for (int kt = 0; kt < nkt; ++kt) {
        const int k0 = kt * 64;
        __syncthreads();
        for (int it = 0; it < 32; ++it) {
            int idx = it * 128 + tid;
            int j = idx >> 6, d = idx & 63;
            float kv = K[(size_t)(k0 + j) * HS + d];
            float vv = V[(size_t)(k0 + j) * HS + d];
            Kt[d * 68 + j] = kv;
            Vs[j * 68 + d] = vv;
        }
        __syncthreads();

        // S = Q K^T for this row
        float4 s4[16];
#pragma unroll
        for (int i = 0; i < 16; i++) s4[i] = make_float4(0.f, 0.f, 0.f, 0.f);
        for (int d = 0; d < 64; ++d) {
            float qd = Qst[d * 129 + tid];
            const float4* krow = (const float4*)(Kt + d * 68);
#pragma unroll
            for (int j4 = 0; j4 < 16; ++j4) {
                float4 kv = krow[j4];
                s4[j4].x += qd * kv.x;
                s4[j4].y += qd * kv.y;
                s4[j4].z += qd * kv.z;
                s4[j4].w += qd * kv.w;
            }
        }

        // causal mask + row max
        float smax = -1e30f;
#pragma unroll
        for (int j4 = 0; j4 < 16; ++j4) {
            int jb = k0 + j4 * 4;
            if (jb + 0 > qrow) s4[j4].x = -1e30f;
            if (jb + 1 > qrow) s4[j4].y = -1e30f;
            if (jb + 2 > qrow) s4[j4].z = -1e30f;
            if (jb + 3 > qrow) s4[j4].w = -1e30f;
            smax = fmaxf(smax, fmaxf(fmaxf(s4[j4].x, s4[j4].y),
                                     fmaxf(s4[j4].z, s4[j4].w)));
        }
        float mnew = fmaxf(m, smax);
        float corr = __expf(m - mnew);
        float psum = 0.f;
#pragma unroll
        for (int j4 = 0; j4 < 16; ++j4) {
            float p0 = __expf(s4[j4].x - mnew);
            float p1 = __expf(s4[j4].y - mnew);
            float p2 = __expf(s4[j4].z - mnew);
            float p3 = __expf(s4[j4].w - mnew);
            psum += (p0 + p1) + (p2 + p3);
            Ps[tid * 65 + j4 * 4 + 0] = p0;
            Ps[tid * 65 + j4 * 4 + 1] = p1;
            Ps[tid * 65 + j4 * 4 + 2] = p2;
            Ps[tid * 65 + j4 * 4 + 3] = p3;
        }
        l = l * corr + psum;
        m = mnew;
#pragma unroll
        for (int i = 0; i < 16; i++) {
            o4[i].x *= corr; o4[i].y *= corr; o4[i].z *= corr; o4[i].w *= corr;
        }

        // O += P V
        for (int j = 0; j < 64; ++j) {
            float pj = Ps[tid * 65 + j];
            const float4* vrow = (const float4*)(Vs + j * 68);
#pragma unroll
            for (int dd = 0; dd < 16; ++dd) {
                float4 vv = vrow[dd];
                o4[dd].x += pj * vv.x;
                o4[dd].y += pj * vv.y;
                o4[dd].z += pj * vv.z;
                o4[dd].w += pj * vv.w;
            }
        }
    }

    const float rl = 1.0f / l;
    const int b = bh >> 4;
    const int h = bh & 15;
    float* orow = g_att + ((size_t)b * TT + q0 + tid) * CEMB + h * HS;
#pragma unroll
    for (int dd = 0; dd < 16; ++dd) {
        float4 ov = make_float4(o4[dd].x * rl, o4[dd].y * rl,
                                o4[dd].z * rl, o4[dd].w * rl);
        *(float4*)(orow + dd * 4) = ov;
    }
}

// ---------------------------------------------------------------------------
// Output projection: g_att [8192,1024] @ Wp [1024,1024] + bp -> d_out
// ---------------------------------------------------------------------------
__global__ void __launch_bounds__(256) proj_gemm(
    const float* __restrict__ Wp,
    const float* __restrict__ bp,
    float* __restrict__ out)
{
    __shared__ float As[8][128];
    __shared__ float Bs[8][128];

    const int tid = threadIdx.x;
    const int tx = tid & 15;
    const int ty = tid >> 4;
    const int m0 = blockIdx.y * 128;
    const int n0 = blockIdx.x * 128;

    float acc[8][8];
#pragma unroll
    for (int i = 0; i < 8; i++)
#pragma unroll
        for (int j = 0; j < 8; j++) acc[i][j] = 0.0f;

    const int a_row = tid >> 1;
    const int a_col = (tid & 1) * 4;
    const int b_row = tid >> 5;
    const int b_col = (tid & 31) * 4;

    const float* Aptr = g_att + (size_t)(m0 + a_row) * CEMB + a_col;
    const float* Bptr = Wp + (size_t)b_row * CEMB + n0 + b_col;

    for (int kb = 0; kb < CEMB; kb += 8) {
        float4 av = *(const float4*)(Aptr + kb);
        As[a_col + 0][a_row] = av.x;
        As[a_col + 1][a_row] = av.y;
        As[a_col + 2][a_row] = av.z;
        As[a_col + 3][a_row] = av.w;
        float4 bv = *(const float4*)(Bptr + (size_t)kb * CEMB);
        *(float4*)&Bs[b_row][b_col] = bv;
        __syncthreads();
#pragma unroll
        for (int k = 0; k < 8; k++) {
            float4 a0 = *(const float4*)&As[k][ty * 8];
            float4 a1 = *(const float4*)&As[k][ty * 8 + 4];
            float4 b0 = *(const float4*)&Bs[k][tx * 8];
            float4 b1 = *(const float4*)&Bs[k][tx * 8 + 4];
            float ar[8] = {a0.x, a0.y, a0.z, a0.w, a1.x, a1.y, a1.z, a1.w};
            float br[8] = {b0.x, b0.y, b0.z, b0.w, b1.x, b1.y, b1.z, b1.w};
#pragma unroll
            for (int i = 0; i < 8; i++)
#pragma unroll
                for (int j = 0; j < 8; j++)
                    acc[i][j] += ar[i] * br[j];
        }
        __syncthreads();
    }

    float4 bias0 = *(const float4*)(bp + n0 + tx * 8);
    float4 bias1 = *(const float4*)(bp + n0 + tx * 8 + 4);
#pragma unroll
    for (int i = 0; i < 8; i++) {
        const int r = m0 + ty * 8 + i;
        float4 o0 = make_float4(acc[i][0] + bias0.x, acc[i][1] + bias0.y,
                                acc[i][2] + bias0.z, acc[i][3] + bias0.w);
        float4 o1 = make_float4(acc[i][4] + bias1.x, acc[i][5] + bias1.y,
                                acc[i][6] + bias1.z, acc[i][7] + bias1.w);
        *(float4*)(out + (size_t)r * CEMB + n0 + tx * 8)     = o0;
        *(float4*)(out + (size_t)r * CEMB + n0 + tx * 8 + 4) = o1;
    }
}

// ---------------------------------------------------------------------------
extern "C" void kernel_launch(void* const* d_in, const int* in_sizes, int n_in,
                              void* d_out, int out_size)
{
    (void)in_sizes; (void)n_in; (void)out_size;
    const float* x  = (const float*)d_in[0];
    const float* Wq = (const float*)d_in[1];
    const float* Wk = (const float*)d_in[2];
    const float* Wv = (const float*)d_in[3];
    const float* Wp = (const float*)d_in[4];
    const float* bp = (const float*)d_in[5];
    float* out = (float*)d_out;

    cudaFuncSetAttribute(flash_kernel,
                         cudaFuncAttributeMaxDynamicSharedMemorySize,
                         FL_SMEM_BYTES);

    dim3 g_qkv(CEMB / 128, MTOT / 128, 3);   // (8, 64, 3)
    qkv_gemm<<<g_qkv, 256>>>(x, Wq, Wk, Wv);

    dim3 g_fl(TT / 128, BB * NHEAD);         // (16, 64)
    flash_kernel<<<g_fl, 128, FL_SMEM_BYTES>>>();

    dim3 g_pr(CEMB / 128, MTOT / 128);       // (8, 64)
    proj_gemm<<<g_pr, 256>>>(Wp, bp, out);
}

// round 2
// speedup vs baseline: 1.4827x; 1.4827x over previous
#include <cuda_runtime.h>
#include <math.h>

#define NHEAD 16
#define HS    64
#define CEMB  1024
#define BB    4
#define TT    2048
#define MTOT  (BB*TT)          // 8192
#define KTILE 16
#define LDA   136              // stride ≡ 8 (mod 32) → conflict-free frag loads

// Scratch (module-load allocated; not a runtime alloc)
__device__ float g_q[(size_t)BB*NHEAD*TT*HS];
__device__ float g_k[(size_t)BB*NHEAD*TT*HS];
__device__ float g_v[(size_t)BB*NHEAD*TT*HS];
__device__ float g_att[(size_t)MTOT*CEMB];

__device__ __forceinline__ float tf32r(float x) {
    unsigned u;
    asm("cvt.rna.tf32.f32 %0, %1;" : "=r"(u) : "f"(x));
    return __uint_as_float(u);
}

__device__ __forceinline__ void mma_tf32(float c[4], const unsigned a[4],
                                         const unsigned b[2]) {
    asm volatile(
        "mma.sync.aligned.m16n8k8.row.col.f32.tf32.tf32.f32 "
        "{%0,%1,%2,%3}, {%4,%5,%6,%7}, {%8,%9}, {%0,%1,%2,%3};\n"
        : "+f"(c[0]), "+f"(c[1]), "+f"(c[2]), "+f"(c[3])
        : "r"(a[0]), "r"(a[1]), "r"(a[2]), "r"(a[3]),
          "r"(b[0]), "r"(b[1]));
}

// ---------------------------------------------------------------------------
// tf32 MMA GEMM 128x128, KTILE=16, 256 threads (8 warps, 4x2 of 32x64).
// mode z: 0=Q(+RoPE), 1=K(+RoPE), 2=V  -> writes [B,H,T,D] scratch
// ---------------------------------------------------------------------------
__global__ void __launch_bounds__(256) qkv_gemm(
    const float* __restrict__ X,
    const float* __restrict__ Wq,
    const float* __restrict__ Wk,
    const float* __restrict__ Wv)
{
    const int mode = blockIdx.z;
    const float* W = (mode == 0) ? Wq : ((mode == 1) ? Wk : Wv);
    float* dst = (mode == 0) ? g_q : ((mode == 1) ? g_k : g_v);

    __shared__ float As[KTILE][LDA];   // [k][m]
    __shared__ float Bs[KTILE][LDA];   // [k][n]

    const int tid  = threadIdx.x;
    const int warp = tid >> 5;
    const int lane = tid & 31;
    const int wm = warp >> 1;          // 0..3
    const int wn = warp & 1;           // 0..1
    const int m0 = blockIdx.y * 128;
    const int n0 = blockIdx.x * 128;

    float acc[2][8][4];
#pragma unroll
    for (int mt = 0; mt < 2; mt++)
#pragma unroll
        for (int nt = 0; nt < 8; nt++)
#pragma unroll
            for (int r = 0; r < 4; r++) acc[mt][nt][r] = 0.0f;

    float4 ra[2], rb[2];
    // A slots: s = tid + 256*i ; m = s>>2, kq = s&3  (coalesced 64B/row)
    // B slots: k = s>>5, nq = s&31                   (coalesced 512B/row)
#pragma unroll
    for (int i = 0; i < 2; i++) {
        int s = tid + 256 * i;
        int am = s >> 2, akq = s & 3;
        ra[i] = *(const float4*)(X + (size_t)(m0 + am) * CEMB + akq * 4);
        int bk = s >> 5, bnq = s & 31;
        rb[i] = *(const float4*)(W + (size_t)bk * CEMB + n0 + bnq * 4);
    }

    for (int kb = 0; kb < CEMB; kb += KTILE) {
        // stage -> smem (tf32-rounded)
#pragma unroll
        for (int i = 0; i < 2; i++) {
            int s = tid + 256 * i;
            int am = s >> 2, akq = s & 3;
            As[akq * 4 + 0][am] = tf32r(ra[i].x);
            As[akq * 4 + 1][am] = tf32r(ra[i].y);
            As[akq * 4 + 2][am] = tf32r(ra[i].z);
            As[akq * 4 + 3][am] = tf32r(ra[i].w);
            int bk = s >> 5, bnq = s & 31;
            float4 t = make_float4(tf32r(rb[i].x), tf32r(rb[i].y),
                                   tf32r(rb[i].z), tf32r(rb[i].w));
            *(float4*)&Bs[bk][bnq * 4] = t;
        }
        __syncthreads();

        if (kb + KTILE < CEMB) {
#pragma unroll
            for (int i = 0; i < 2; i++) {
                int s = tid + 256 * i;
                int am = s >> 2, akq = s & 3;
                ra[i] = *(const float4*)(X + (size_t)(m0 + am) * CEMB +
                                         kb + KTILE + akq * 4);
                int bk = s >> 5, bnq = s & 31;
                rb[i] = *(const float4*)(W + (size_t)(kb + KTILE + bk) * CEMB +
                                         n0 + bnq * 4);
            }
        }

#pragma unroll
        for (int ks = 0; ks < KTILE; ks += 8) {
            const int kr = ks + (lane & 3);
            const int mrow = wm * 32 + (lane >> 2);
            const int ncol = wn * 64 + (lane >> 2);
            unsigned af[2][4], bf[8][2];
#pragma unroll
            for (int mt = 0; mt < 2; mt++) {
                af[mt][0] = __float_as_uint(As[kr    ][mrow + mt * 16    ]);
                af[mt][1] = __float_as_uint(As[kr    ][mrow + mt * 16 + 8]);
                af[mt][2] = __float_as_uint(As[kr + 4][mrow + mt * 16    ]);
                af[mt][3] = __float_as_uint(As[kr + 4][mrow + mt * 16 + 8]);
            }
#pragma unroll
            for (int nt = 0; nt < 8; nt++) {
                bf[nt][0] = __float_as_uint(Bs[kr    ][ncol + nt * 8]);
                bf[nt][1] = __float_as_uint(Bs[kr + 4][ncol + nt * 8]);
            }
#pragma unroll
            for (int mt = 0; mt < 2; mt++)
#pragma unroll
                for (int nt = 0; nt < 8; nt++)
                    mma_tf32(acc[mt][nt], af[mt], bf[nt]);
        }
        __syncthreads();
    }

    // Epilogue: RoPE on (even,odd) column pair = (c0,c1)/(c2,c3)
    const float L2T = 13.287712379549449f / 64.0f;  // log2(10000)/64
#pragma unroll
    for (int mt = 0; mt < 2; mt++) {
        const int row_base = m0 + wm * 32 + mt * 16 + (lane >> 2);
#pragma unroll
        for (int nt = 0; nt < 8; nt++) {
            const int col = n0 + wn * 64 + nt * 8 + (lane & 3) * 2;
            const int h = col >> 6;
            const int d = col & 63;
#pragma unroll
            for (int half = 0; half < 2; half++) {
                const int row = row_base + half * 8;
                const int b = row >> 11;
                const int t = row & 2047;
                float x0 = acc[mt][nt][half * 2];
                float x1 = acc[mt][nt][half * 2 + 1];
                float o0 = x0, o1 = x1;
                if (mode < 2) {
                    float inv = exp2f(-(float)d * L2T);
                    float ang = (float)t * inv;
                    float sv, cv;
                    sincosf(ang, &sv, &cv);
                    o0 = x0 * cv - x1 * sv;
                    o1 = x0 * sv + x1 * cv;
                }
                size_t base = ((size_t)(b * NHEAD + h) * TT + t) * HS + d;
                *(float2*)(dst + base) = make_float2(o0, o1);
            }
        }
    }
}

// ---------------------------------------------------------------------------
// Flash attention fp32, causal. One thread per query row. BM=128, BN=64.
// ---------------------------------------------------------------------------
#define FL_QST (64 * 129)
#define FL_KT  (64 * 68)
#define FL_VS  (64 * 68)
#define FL_PS  (128 * 65)
#define FL_SMEM_FLOATS (FL_QST + FL_KT + FL_VS + FL_PS)
#define FL_SMEM_BYTES  (FL_SMEM_FLOATS * 4)

__global__ void __launch_bounds__(128) flash_kernel()
{
    extern __shared__ float sm[];
    float* Qst = sm;
    float* Kt  = Qst + FL_QST;
    float* Vs  = Kt + FL_KT;
    float* Ps  = Vs + FL_VS;

    const int tid = threadIdx.x;
    const int q0  = blockIdx.x * 128;
    const int bh  = blockIdx.y;

    const float* Q = g_q + (size_t)bh * TT * HS;
    const float* K = g_k + (size_t)bh * TT * HS;
    const float* V = g_v + (size_t)bh * TT * HS;

    for (int it = 0; it < 64; ++it) {
        int idx = it * 128 + tid;
        int r = idx >> 6, d = idx & 63;
        Qst[d * 129 + r] = Q[(size_t)(q0 + r) * HS + d] * 0.125f;
    }

    float4 o4[16];
#pragma unroll
    for (int i = 0; i < 16; i++) o4[i] = make_float4(0.f, 0.f, 0.f, 0.f);
    float m = -1e30f, l = 0.f;

    const int qrow = q0 + tid;
    const int nkt = (q0 >> 6) + 2;

    for (int kt = 0; kt < nkt; ++kt) {
        const int k0 = kt * 64;
        __syncthreads();
        for (int it = 0; it < 32; ++it) {
            int idx = it * 128 + tid;
            int j = idx >> 6, d = idx & 63;
            float kv = K[(size_t)(k0 + j) * HS + d];
            float vv = V[(size_t)(k0 + j) * HS + d];
            Kt[d * 68 + j] = kv;
            Vs[j * 68 + d] = vv;
        }
        __syncthreads();

        float4 s4[16];
#pragma unroll
        for (int i = 0; i < 16; i++) s4[i] = make_float4(0.f, 0.f, 0.f, 0.f);
        for (int d = 0; d < 64; ++d) {
            float qd = Qst[d * 129 + tid];
            const float4* krow = (const float4*)(Kt + d * 68);
#pragma unroll
            for (int j4 = 0; j4 < 16; ++j4) {
                float4 kv = krow[j4];
                s4[j4].x += qd * kv.x;
                s4[j4].y += qd * kv.y;
                s4[j4].z += qd * kv.z;
                s4[j4].w += qd * kv.w;
            }
        }

        float smax = -1e30f;
#pragma unroll
        for (int j4 = 0; j4 < 16; ++j4) {
            int jb = k0 + j4 * 4;
            if (jb + 0 > qrow) s4[j4].x = -1e30f;
            if (jb + 1 > qrow) s4[j4].y = -1e30f;
            if (jb + 2 > qrow) s4[j4].z = -1e30f;
            if (jb + 3 > qrow) s4[j4].w = -1e30f;
            smax = fmaxf(smax, fmaxf(fmaxf(s4[j4].x, s4[j4].y),
                                     fmaxf(s4[j4].z, s4[j4].w)));
        }
        float mnew = fmaxf(m, smax);
        float corr = __expf(m - mnew);
        float psum = 0.f;
#pragma unroll
        for (int j4 = 0; j4 < 16; ++j4) {
            float p0 = __expf(s4[j4].x - mnew);
            float p1 = __expf(s4[j4].y - mnew);
            float p2 = __expf(s4[j4].z - mnew);
            float p3 = __expf(s4[j4].w - mnew);
            psum += (p0 + p1) + (p2 + p3);
            Ps[tid * 65 + j4 * 4 + 0] = p0;
            Ps[tid * 65 + j4 * 4 + 1] = p1;
            Ps[tid * 65 + j4 * 4 + 2] = p2;
            Ps[tid * 65 + j4 * 4 + 3] = p3;
        }
        l = l * corr + psum;
        m = mnew;
#pragma unroll
        for (int i = 0; i < 16; i++) {
            o4[i].x *= corr; o4[i].y *= corr; o4[i].z *= corr; o4[i].w *= corr;
        }

        for (int j = 0; j < 64; ++j) {
            float pj = Ps[tid * 65 + j];
            const float4* vrow = (const float4*)(Vs + j * 68);
#pragma unroll
            for (int dd = 0; dd < 16; ++dd) {
                float4 vv = vrow[dd];
                o4[dd].x += pj * vv.x;
                o4[dd].y += pj * vv.y;
                o4[dd].z += pj * vv.z;
                o4[dd].w += pj * vv.w;
            }
        }
    }

    const float rl = 1.0f / l;
    const int b = bh >> 4;
    const int h = bh & 15;
    float* orow = g_att + ((size_t)b * TT + q0 + tid) * CEMB + h * HS;
#pragma unroll
    for (int dd = 0; dd < 16; ++dd) {
        float4 ov = make_float4(o4[dd].x * rl, o4[dd].y * rl,
                                o4[dd].z * rl, o4[dd].w * rl);
        *(float4*)(orow + dd * 4) = ov;
    }
}

// ---------------------------------------------------------------------------
// Output projection (tf32 MMA): g_att [8192,1024] @ Wp + bp -> d_out
// ---------------------------------------------------------------------------
__global__ void __launch_bounds__(256) proj_gemm(
    const float* __restrict__ Wp,
    const float* __restrict__ bp,
    float* __restrict__ out)
{
    __shared__ float As[KTILE][LDA];
    __shared__ float Bs[KTILE][LDA];

    const int tid  = threadIdx.x;
    const int warp = tid >> 5;
    const int lane = tid & 31;
    const int wm = warp >> 1;
    const int wn = warp & 1;
    const int m0 = blockIdx.y * 128;
    const int n0 = blockIdx.x * 128;

    float acc[2][8][4];
#pragma unroll
    for (int mt = 0; mt < 2; mt++)
#pragma unroll
        for (int nt = 0; nt < 8; nt++)
#pragma unroll
            for (int r = 0; r < 4; r++) acc[mt][nt][r] = 0.0f;

    float4 ra[2], rb[2];
#pragma unroll
    for (int i = 0; i < 2; i++) {
        int s = tid + 256 * i;
        int am = s >> 2, akq = s & 3;
        ra[i] = *(const float4*)(g_att + (size_t)(m0 + am) * CEMB + akq * 4);
        int bk = s >> 5, bnq = s & 31;
        rb[i] = *(const float4*)(Wp + (size_t)bk * CEMB + n0 + bnq * 4);
    }

    for (int kb = 0; kb < CEMB; kb += KTILE) {
#pragma unroll
        for (int i = 0; i < 2; i++) {
            int s = tid + 256 * i;
            int am = s >> 2, akq = s & 3;
            As[akq * 4 + 0][am] = tf32r(ra[i].x);
            As[akq * 4 + 1][am] = tf32r(ra[i].y);
            As[akq * 4 + 2][am] = tf32r(ra[i].z);
            As[akq * 4 + 3][am] = tf32r(ra[i].w);
            int bk = s >> 5, bnq = s & 31;
            float4 t = make_float4(tf32r(rb[i].x), tf32r(rb[i].y),
                                   tf32r(rb[i].z), tf32r(rb[i].w));
            *(float4*)&Bs[bk][bnq * 4] = t;
        }
        __syncthreads();

        if (kb + KTILE < CEMB) {
#pragma unroll
            for (int i = 0; i < 2; i++) {
                int s = tid + 256 * i;
                int am = s >> 2, akq = s & 3;
                ra[i] = *(const float4*)(g_att + (size_t)(m0 + am) * CEMB +
                                         kb + KTILE + akq * 4);
                int bk = s >> 5, bnq = s & 31;
                rb[i] = *(const float4*)(Wp + (size_t)(kb + KTILE + bk) * CEMB +
                                         n0 + bnq * 4);
            }
        }

#pragma unroll
        for (int ks = 0; ks < KTILE; ks += 8) {
            const int kr = ks + (lane & 3);
            const int mrow = wm * 32 + (lane >> 2);
            const int ncol = wn * 64 + (lane >> 2);
            unsigned af[2][4], bf[8][2];
#pragma unroll
            for (int mt = 0; mt < 2; mt++) {
                af[mt][0] = __float_as_uint(As[kr    ][mrow + mt * 16    ]);
                af[mt][1] = __float_as_uint(As[kr    ][mrow + mt * 16 + 8]);
                af[mt][2] = __float_as_uint(As[kr + 4][mrow + mt * 16    ]);
                af[mt][3] = __float_as_uint(As[kr + 4][mrow + mt * 16 + 8]);
            }
#pragma unroll
            for (int nt = 0; nt < 8; nt++) {
                bf[nt][0] = __float_as_uint(Bs[kr    ][ncol + nt * 8]);
                bf[nt][1] = __float_as_uint(Bs[kr + 4][ncol + nt * 8]);
            }
#pragma unroll
            for (int mt = 0; mt < 2; mt++)
#pragma unroll
                for (int nt = 0; nt < 8; nt++)
                    mma_tf32(acc[mt][nt], af[mt], bf[nt]);
        }
        __syncthreads();
    }

#pragma unroll
    for (int mt = 0; mt < 2; mt++) {
        const int row_base = m0 + wm * 32 + mt * 16 + (lane >> 2);
#pragma unroll
        for (int nt = 0; nt < 8; nt++) {
            const int col = n0 + wn * 64 + nt * 8 + (lane & 3) * 2;
            const float b0 = bp[col];
            const float b1 = bp[col + 1];
#pragma unroll
            for (int half = 0; half < 2; half++) {
                const int row = row_base + half * 8;
                *(float2*)(out + (size_t)row * CEMB + col) =
                    make_float2(acc[mt][nt][half * 2]     + b0,
                                acc[mt][nt][half * 2 + 1] + b1);
            }
        }
    }
}

// ---------------------------------------------------------------------------
extern "C" void kernel_launch(void* const* d_in, const int* in_sizes, int n_in,
                              void* d_out, int out_size)
{
    (void)in_sizes; (void)n_in; (void)out_size;
    const float* x  = (const float*)d_in[0];
    const float* Wq = (const float*)d_in[1];
    const float* Wk = (const float*)d_in[2];
    const float* Wv = (const float*)d_in[3];
    const float* Wp = (const float*)d_in[4];
    const float* bp = (const float*)d_in[5];
    float* out = (float*)d_out;

    cudaFuncSetAttribute(flash_kernel,
                         cudaFuncAttributeMaxDynamicSharedMemorySize,
                         FL_SMEM_BYTES);

    dim3 g_qkv(CEMB / 128, MTOT / 128, 3);   // (8, 64, 3)
    qkv_gemm<<<g_qkv, 256>>>(x, Wq, Wk, Wv);

    dim3 g_fl(TT / 128, BB * NHEAD);         // (16, 64)
    flash_kernel<<<g_fl, 128, FL_SMEM_BYTES>>>();

    dim3 g_pr(CEMB / 128, MTOT / 128);       // (8, 64)
    proj_gemm<<<g_pr, 256>>>(Wp, bp, out);
}

// round 3
// speedup vs baseline: 2.5834x; 1.7423x over previous
#include <cuda_runtime.h>
#include <math.h>

#define NHEAD 16
#define HS    64
#define CEMB  1024
#define BB    4
#define TT    2048
#define MTOT  (BB*TT)          // 8192
#define KTILE 16
#define LDA   136              // stride ≡ 8 (mod 32) → conflict-free frag loads

// Scratch (module-load allocated; not a runtime alloc)
__device__ float g_q[(size_t)BB*NHEAD*TT*HS];
__device__ float g_k[(size_t)BB*NHEAD*TT*HS];
__device__ float g_v[(size_t)BB*NHEAD*TT*HS];
__device__ float g_att[(size_t)MTOT*CEMB];

__device__ __forceinline__ float tf32r(float x) {
    unsigned u;
    asm("cvt.rna.tf32.f32 %0, %1;" : "=r"(u) : "f"(x));
    return __uint_as_float(u);
}

__device__ __forceinline__ void mma_tf32(float c[4], const unsigned a[4],
                                         const unsigned b[2]) {
    asm volatile(
        "mma.sync.aligned.m16n8k8.row.col.f32.tf32.tf32.f32 "
        "{%0,%1,%2,%3}, {%4,%5,%6,%7}, {%8,%9}, {%0,%1,%2,%3};\n"
        : "+f"(c[0]), "+f"(c[1]), "+f"(c[2]), "+f"(c[3])
        : "r"(a[0]), "r"(a[1]), "r"(a[2]), "r"(a[3]),
          "r"(b[0]), "r"(b[1]));
}

// ---------------------------------------------------------------------------
// tf32 MMA GEMM 128x128, KTILE=16, 256 threads (8 warps, 4x2 of 32x64).
// mode z: 0=Q(+RoPE), 1=K(+RoPE), 2=V  -> writes [B,H,T,D] scratch
// ---------------------------------------------------------------------------
__global__ void __launch_bounds__(256) qkv_gemm(
    const float* __restrict__ X,
    const float* __restrict__ Wq,
    const float* __restrict__ Wk,
    const float* __restrict__ Wv)
{
    const int mode = blockIdx.z;
    const float* W = (mode == 0) ? Wq : ((mode == 1) ? Wk : Wv);
    float* dst = (mode == 0) ? g_q : ((mode == 1) ? g_k : g_v);

    __shared__ float As[KTILE][LDA];   // [k][m]
    __shared__ float Bs[KTILE][LDA];   // [k][n]

    const int tid  = threadIdx.x;
    const int warp = tid >> 5;
    const int lane = tid & 31;
    const int wm = warp >> 1;          // 0..3
    const int wn = warp & 1;           // 0..1
    const int m0 = blockIdx.y * 128;
    const int n0 = blockIdx.x * 128;

    float acc[2][8][4];
#pragma unroll
    for (int mt = 0; mt < 2; mt++)
#pragma unroll
        for (int nt = 0; nt < 8; nt++)
#pragma unroll
            for (int r = 0; r < 4; r++) acc[mt][nt][r] = 0.0f;

    float4 ra[2], rb[2];
#pragma unroll
    for (int i = 0; i < 2; i++) {
        int s = tid + 256 * i;
        int am = s >> 2, akq = s & 3;
        ra[i] = *(const float4*)(X + (size_t)(m0 + am) * CEMB + akq * 4);
        int bk = s >> 5, bnq = s & 31;
        rb[i] = *(const float4*)(W + (size_t)bk * CEMB + n0 + bnq * 4);
    }

    for (int kb = 0; kb < CEMB; kb += KTILE) {
#pragma unroll
        for (int i = 0; i < 2; i++) {
            int s = tid + 256 * i;
            int am = s >> 2, akq = s & 3;
            As[akq * 4 + 0][am] = tf32r(ra[i].x);
            As[akq * 4 + 1][am] = tf32r(ra[i].y);
            As[akq * 4 + 2][am] = tf32r(ra[i].z);
            As[akq * 4 + 3][am] = tf32r(ra[i].w);
            int bk = s >> 5, bnq = s & 31;
            float4 t = make_float4(tf32r(rb[i].x), tf32r(rb[i].y),
                                   tf32r(rb[i].z), tf32r(rb[i].w));
            *(float4*)&Bs[bk][bnq * 4] = t;
        }
        __syncthreads();

        if (kb + KTILE < CEMB) {
#pragma unroll
            for (int i = 0; i < 2; i++) {
                int s = tid + 256 * i;
                int am = s >> 2, akq = s & 3;
                ra[i] = *(const float4*)(X + (size_t)(m0 + am) * CEMB +
                                         kb + KTILE + akq * 4);
                int bk = s >> 5, bnq = s & 31;
                rb[i] = *(const float4*)(W + (size_t)(kb + KTILE + bk) * CEMB +
                                         n0 + bnq * 4);
            }
        }

#pragma unroll
        for (int ks = 0; ks < KTILE; ks += 8) {
            const int kr = ks + (lane & 3);
            const int mrow = wm * 32 + (lane >> 2);
            const int ncol = wn * 64 + (lane >> 2);
            unsigned af[2][4], bf[8][2];
#pragma unroll
            for (int mt = 0; mt < 2; mt++) {
                af[mt][0] = __float_as_uint(As[kr    ][mrow + mt * 16    ]);
                af[mt][1] = __float_as_uint(As[kr    ][mrow + mt * 16 + 8]);
                af[mt][2] = __float_as_uint(As[kr + 4][mrow + mt * 16    ]);
                af[mt][3] = __float_as_uint(As[kr + 4][mrow + mt * 16 + 8]);
            }
#pragma unroll
            for (int nt = 0; nt < 8; nt++) {
                bf[nt][0] = __float_as_uint(Bs[kr    ][ncol + nt * 8]);
                bf[nt][1] = __float_as_uint(Bs[kr + 4][ncol + nt * 8]);
            }
#pragma unroll
            for (int mt = 0; mt < 2; mt++)
#pragma unroll
                for (int nt = 0; nt < 8; nt++)
                    mma_tf32(acc[mt][nt], af[mt], bf[nt]);
        }
        __syncthreads();
    }

    const float L2T = 13.287712379549449f / 64.0f;  // log2(10000)/64
#pragma unroll
    for (int mt = 0; mt < 2; mt++) {
        const int row_base = m0 + wm * 32 + mt * 16 + (lane >> 2);
#pragma unroll
        for (int nt = 0; nt < 8; nt++) {
            const int col = n0 + wn * 64 + nt * 8 + (lane & 3) * 2;
            const int h = col >> 6;
            const int d = col & 63;
#pragma unroll
            for (int half = 0; half < 2; half++) {
                const int row = row_base + half * 8;
                const int b = row >> 11;
                const int t = row & 2047;
                float x0 = acc[mt][nt][half * 2];
                float x1 = acc[mt][nt][half * 2 + 1];
                float o0 = x0, o1 = x1;
                if (mode < 2) {
                    float inv = exp2f(-(float)d * L2T);
                    float ang = (float)t * inv;
                    float sv, cv;
                    sincosf(ang, &sv, &cv);
                    o0 = x0 * cv - x1 * sv;
                    o1 = x0 * sv + x1 * cv;
                }
                size_t base = ((size_t)(b * NHEAD + h) * TT + t) * HS + d;
                *(float2*)(dst + base) = make_float2(o0, o1);
            }
        }
    }
}

// ---------------------------------------------------------------------------
// Flash attention on tensor pipe. BM=64 (4 warps x m16), BN=64, D=64.
// QK^T: tf32x3 (q,k hi/lo).  P.V: V hi/lo split, P plain tf32.
// Layouts (floats): Qs[64][76], Khi[64][76], Klo[64][76] row-major [row][d],
//                   Vs2 float2[64][70] (hi,lo interleaved), Ps[64][68].
// ---------------------------------------------------------------------------
#define QS_STR 76
#define KS_STR 76
#define VS_STR 70   // in float2 units
#define PS_STR 68

#define FA_SMEM_FLOATS (64*QS_STR + 2*64*KS_STR + 64*VS_STR*2 + 64*PS_STR)
#define FA_SMEM_BYTES  (FA_SMEM_FLOATS * 4)

__global__ void __launch_bounds__(128) flash_mma()
{
    extern __shared__ float sm[];
    float*  Qs  = sm;                       // [64][76]
    float*  Khi = Qs  + 64 * QS_STR;        // [64][76]
    float*  Klo = Khi + 64 * KS_STR;        // [64][76]
    float2* Vs2 = (float2*)(Klo + 64 * KS_STR);  // [64][70] (hi,lo)
    float*  Ps  = (float*)(Vs2 + 64 * VS_STR);   // [64][68]

    const int tid  = threadIdx.x;
    const int warp = tid >> 5;
    const int lane = tid & 31;
    const int qt   = gridDim.x - 1 - blockIdx.x;   // big tiles first
    const int q0   = qt * 64;
    const int bh   = blockIdx.y;

    const float* Q = g_q + (size_t)bh * TT * HS;
    const float* K = g_k + (size_t)bh * TT * HS;
    const float* V = g_v + (size_t)bh * TT * HS;

    // ---- load Q tile (scaled), 1024 float4 / 128 thr = 8 each
#pragma unroll
    for (int i = 0; i < 8; i++) {
        int s = i * 128 + tid;
        int r = s >> 4, dq = (s & 15) * 4;
        float4 v = *(const float4*)(Q + (size_t)(q0 + r) * HS + dq);
        v.x *= 0.125f; v.y *= 0.125f; v.z *= 0.125f; v.w *= 0.125f;
        *(float4*)(Qs + r * QS_STR + dq) = v;
    }
    __syncthreads();

    // ---- preload Q frags into registers, split hi/lo
    const int lrow = warp * 16 + (lane >> 2);   // local row 0..63
    unsigned qh[8][4], ql[8][4];
#pragma unroll
    for (int ks = 0; ks < 8; ks++) {
        const int kd = ks * 8 + (lane & 3);
        float v0 = Qs[lrow * QS_STR + kd];
        float v1 = Qs[(lrow + 8) * QS_STR + kd];
        float v2 = Qs[lrow * QS_STR + kd + 4];
        float v3 = Qs[(lrow + 8) * QS_STR + kd + 4];
        float h0 = tf32r(v0), h1 = tf32r(v1), h2 = tf32r(v2), h3 = tf32r(v3);
        qh[ks][0] = __float_as_uint(h0);
        qh[ks][1] = __float_as_uint(h1);
        qh[ks][2] = __float_as_uint(h2);
        qh[ks][3] = __float_as_uint(h3);
        ql[ks][0] = __float_as_uint(tf32r(v0 - h0));
        ql[ks][1] = __float_as_uint(tf32r(v1 - h1));
        ql[ks][2] = __float_as_uint(tf32r(v2 - h2));
        ql[ks][3] = __float_as_uint(tf32r(v3 - h3));
    }

    float o[8][4];
#pragma unroll
    for (int nt = 0; nt < 8; nt++)
#pragma unroll
        for (int r = 0; r < 4; r++) o[nt][r] = 0.0f;
    float m_a = -1e30f, m_b = -1e30f, l_a = 0.0f, l_b = 0.0f;

    const int grow_a = q0 + lrow;      // global q row for c0,c1
    const int grow_b = grow_a + 8;     // for c2,c3

    for (int kt = 0; kt <= qt; kt++) {
        const int k0 = kt * 64;
        __syncthreads();   // previous iter consumers done
        // ---- load K (split) and V (split) tiles
#pragma unroll
        for (int i = 0; i < 8; i++) {
            int s = i * 128 + tid;
            int j = s >> 4, dq = (s & 15) * 4;
            float4 kv = *(const float4*)(K + (size_t)(k0 + j) * HS + dq);
            float h0 = tf32r(kv.x), h1 = tf32r(kv.y),
                  h2 = tf32r(kv.z), h3 = tf32r(kv.w);
            *(float4*)(Khi + j * KS_STR + dq) = make_float4(h0, h1, h2, h3);
            *(float4*)(Klo + j * KS_STR + dq) =
                make_float4(tf32r(kv.x - h0), tf32r(kv.y - h1),
                            tf32r(kv.z - h2), tf32r(kv.w - h3));
            float4 vv = *(const float4*)(V + (size_t)(k0 + j) * HS + dq);
            float vh0 = tf32r(vv.x), vh1 = tf32r(vv.y),
                  vh2 = tf32r(vv.z), vh3 = tf32r(vv.w);
            Vs2[j * VS_STR + dq + 0] = make_float2(vh0, tf32r(vv.x - vh0));
            Vs2[j * VS_STR + dq + 1] = make_float2(vh1, tf32r(vv.y - vh1));
            Vs2[j * VS_STR + dq + 2] = make_float2(vh2, tf32r(vv.z - vh2));
            Vs2[j * VS_STR + dq + 3] = make_float2(vh3, tf32r(vv.w - vh3));
        }
        __syncthreads();

        // ---- S = Q K^T (tf32x3)
        float s4[8][4];
#pragma unroll
        for (int nt = 0; nt < 8; nt++)
#pragma unroll
            for (int r = 0; r < 4; r++) s4[nt][r] = 0.0f;

#pragma unroll
        for (int ks = 0; ks < 8; ks++) {
            const int kd = ks * 8 + (lane & 3);
#pragma unroll
            for (int nt = 0; nt < 8; nt++) {
                const int j = nt * 8 + (lane >> 2);
                unsigned bh2[2], bl2[2];
                bh2[0] = __float_as_uint(Khi[j * KS_STR + kd]);
                bh2[1] = __float_as_uint(Khi[j * KS_STR + kd + 4]);
                bl2[0] = __float_as_uint(Klo[j * KS_STR + kd]);
                bl2[1] = __float_as_uint(Klo[j * KS_STR + kd + 4]);
                mma_tf32(s4[nt], qh[ks], bh2);
                mma_tf32(s4[nt], qh[ks], bl2);
                mma_tf32(s4[nt], ql[ks], bh2);
            }
        }

        // ---- causal mask (diagonal tile only)
        if (kt == qt) {
#pragma unroll
            for (int nt = 0; nt < 8; nt++) {
                const int c = k0 + nt * 8 + (lane & 3) * 2;
                if (c     > grow_a) s4[nt][0] = -1e30f;
                if (c + 1 > grow_a) s4[nt][1] = -1e30f;
                if (c     > grow_b) s4[nt][2] = -1e30f;
                if (c + 1 > grow_b) s4[nt][3] = -1e30f;
            }
        }

        // ---- online softmax (rows a: c0,c1; rows b: c2,c3)
        float ma = -1e30f, mb = -1e30f;
#pragma unroll
        for (int nt = 0; nt < 8; nt++) {
            ma = fmaxf(ma, fmaxf(s4[nt][0], s4[nt][1]));
            mb = fmaxf(mb, fmaxf(s4[nt][2], s4[nt][3]));
        }
        ma = fmaxf(ma, __shfl_xor_sync(0xffffffffu, ma, 1));
        ma = fmaxf(ma, __shfl_xor_sync(0xffffffffu, ma, 2));
        mb = fmaxf(mb, __shfl_xor_sync(0xffffffffu, mb, 1));
        mb = fmaxf(mb, __shfl_xor_sync(0xffffffffu, mb, 2));

        const float mna = fmaxf(m_a, ma);
        const float mnb = fmaxf(m_b, mb);
        const float ca = __expf(m_a - mna);
        const float cb = __expf(m_b - mnb);

        float sa = 0.0f, sb = 0.0f;
#pragma unroll
        for (int nt = 0; nt < 8; nt++) {
            float p0 = __expf(s4[nt][0] - mna);
            float p1 = __expf(s4[nt][1] - mna);
            float p2 = __expf(s4[nt][2] - mnb);
            float p3 = __expf(s4[nt][3] - mnb);
            sa += p0 + p1;
            sb += p2 + p3;
            const int col = nt * 8 + (lane & 3) * 2;
            *(float2*)(Ps + lrow * PS_STR + col) =
                make_float2(tf32r(p0), tf32r(p1));
            *(float2*)(Ps + (lrow + 8) * PS_STR + col) =
                make_float2(tf32r(p2), tf32r(p3));
        }
        sa += __shfl_xor_sync(0xffffffffu, sa, 1);
        sa += __shfl_xor_sync(0xffffffffu, sa, 2);
        sb += __shfl_xor_sync(0xffffffffu, sb, 1);
        sb += __shfl_xor_sync(0xffffffffu, sb, 2);
        l_a = l_a * ca + sa;  m_a = mna;
        l_b = l_b * cb + sb;  m_b = mnb;

#pragma unroll
        for (int nt = 0; nt < 8; nt++) {
            o[nt][0] *= ca; o[nt][1] *= ca;
            o[nt][2] *= cb; o[nt][3] *= cb;
        }
        __syncwarp();   // P strip is warp-private

        // ---- O += P V  (V hi/lo)
#pragma unroll
        for (int ks = 0; ks < 8; ks++) {
            const int kj = ks * 8 + (lane & 3);
            unsigned pa[4];
            pa[0] = __float_as_uint(Ps[lrow * PS_STR + kj]);
            pa[1] = __float_as_uint(Ps[(lrow + 8) * PS_STR + kj]);
            pa[2] = __float_as_uint(Ps[lrow * PS_STR + kj + 4]);
            pa[3] = __float_as_uint(Ps[(lrow + 8) * PS_STR + kj + 4]);
#pragma unroll
            for (int nt = 0; nt < 8; nt++) {
                const int dcol = nt * 8 + (lane >> 2);
                float2 v0 = Vs2[kj * VS_STR + dcol];
                float2 v1 = Vs2[(kj + 4) * VS_STR + dcol];
                unsigned bvh[2] = { __float_as_uint(v0.x),
                                    __float_as_uint(v1.x) };
                unsigned bvl[2] = { __float_as_uint(v0.y),
                                    __float_as_uint(v1.y) };
                mma_tf32(o[nt], pa, bvh);
                mma_tf32(o[nt], pa, bvl);
            }
        }
    }

    // ---- epilogue: divide by l, write [B,T,H*D]
    const float rla = 1.0f / l_a;
    const float rlb = 1.0f / l_b;
    const int b = bh >> 4;
    const int h = bh & 15;
    float* oa = g_att + ((size_t)b * TT + grow_a) * CEMB + h * HS;
    float* ob = g_att + ((size_t)b * TT + grow_b) * CEMB + h * HS;
#pragma unroll
    for (int nt = 0; nt < 8; nt++) {
        const int col = nt * 8 + (lane & 3) * 2;
        *(float2*)(oa + col) = make_float2(o[nt][0] * rla, o[nt][1] * rla);
        *(float2*)(ob + col) = make_float2(o[nt][2] * rlb, o[nt][3] * rlb);
    }
}

// ---------------------------------------------------------------------------
// Output projection (tf32 MMA): g_att [8192,1024] @ Wp + bp -> d_out
// ---------------------------------------------------------------------------
__global__ void __launch_bounds__(256) proj_gemm(
    const float* __restrict__ Wp,
    const float* __restrict__ bp,
    float* __restrict__ out)
{
    __shared__ float As[KTILE][LDA];
    __shared__ float Bs[KTILE][LDA];

    const int tid  = threadIdx.x;
    const int warp = tid >> 5;
    const int lane = tid & 31;
    const int wm = warp >> 1;
    const int wn = warp & 1;
    const int m0 = blockIdx.y * 128;
    const int n0 = blockIdx.x * 128;

    float acc[2][8][4];
#pragma unroll
    for (int mt = 0; mt < 2; mt++)
#pragma unroll
        for (int nt = 0; nt < 8; nt++)
#pragma unroll
            for (int r = 0; r < 4; r++) acc[mt][nt][r] = 0.0f;

    float4 ra[2], rb[2];
#pragma unroll
    for (int i = 0; i < 2; i++) {
        int s = tid + 256 * i;
        int am = s >> 2, akq = s & 3;
        ra[i] = *(const float4*)(g_att + (size_t)(m0 + am) * CEMB + akq * 4);
        int bk = s >> 5, bnq = s & 31;
        rb[i] = *(const float4*)(Wp + (size_t)bk * CEMB + n0 + bnq * 4);
    }

    for (int kb = 0; kb < CEMB; kb += KTILE) {
#pragma unroll
        for (int i = 0; i < 2; i++) {
            int s = tid + 256 * i;
            int am = s >> 2, akq = s & 3;
            As[akq * 4 + 0][am] = tf32r(ra[i].x);
            As[akq * 4 + 1][am] = tf32r(ra[i].y);
            As[akq * 4 + 2][am] = tf32r(ra[i].z);
            As[akq * 4 + 3][am] = tf32r(ra[i].w);
            int bk = s >> 5, bnq = s & 31;
            float4 t = make_float4(tf32r(rb[i].x), tf32r(rb[i].y),
                                   tf32r(rb[i].z), tf32r(rb[i].w));
            *(float4*)&Bs[bk][bnq * 4] = t;
        }
        __syncthreads();

        if (kb + KTILE < CEMB) {
#pragma unroll
            for (int i = 0; i < 2; i++) {
                int s = tid + 256 * i;
                int am = s >> 2, akq = s & 3;
                ra[i] = *(const float4*)(g_att + (size_t)(m0 + am) * CEMB +
                                         kb + KTILE + akq * 4);
                int bk = s >> 5, bnq = s & 31;
                rb[i] = *(const float4*)(Wp + (size_t)(kb + KTILE + bk) * CEMB +
                                         n0 + bnq * 4);
            }
        }

#pragma unroll
        for (int ks = 0; ks < KTILE; ks += 8) {
            const int kr = ks + (lane & 3);
            const int mrow = wm * 32 + (lane >> 2);
            const int ncol = wn * 64 + (lane >> 2);
            unsigned af[2][4], bf[8][2];
#pragma unroll
            for (int mt = 0; mt < 2; mt++) {
                af[mt][0] = __float_as_uint(As[kr    ][mrow + mt * 16    ]);
                af[mt][1] = __float_as_uint(As[kr    ][mrow + mt * 16 + 8]);
                af[mt][2] = __float_as_uint(As[kr + 4][mrow + mt * 16    ]);
                af[mt][3] = __float_as_uint(As[kr + 4][mrow + mt * 16 + 8]);
            }
#pragma unroll
            for (int nt = 0; nt < 8; nt++) {
                bf[nt][0] = __float_as_uint(Bs[kr    ][ncol + nt * 8]);
                bf[nt][1] = __float_as_uint(Bs[kr + 4][ncol + nt * 8]);
            }
#pragma unroll
            for (int mt = 0; mt < 2; mt++)
#pragma unroll
                for (int nt = 0; nt < 8; nt++)
                    mma_tf32(acc[mt][nt], af[mt], bf[nt]);
        }
        __syncthreads();
    }

#pragma unroll
    for (int mt = 0; mt < 2; mt++) {
        const int row_base = m0 + wm * 32 + mt * 16 + (lane >> 2);
#pragma unroll
        for (int nt = 0; nt < 8; nt++) {
            const int col = n0 + wn * 64 + nt * 8 + (lane & 3) * 2;
            const float b0 = bp[col];
            const float b1 = bp[col + 1];
#pragma unroll
            for (int half = 0; half < 2; half++) {
                const int row = row_base + half * 8;
                *(float2*)(out + (size_t)row * CEMB + col) =
                    make_float2(acc[mt][nt][half * 2]     + b0,
                                acc[mt][nt][half * 2 + 1] + b1);
            }
        }
    }
}

// ---------------------------------------------------------------------------
extern "C" void kernel_launch(void* const* d_in, const int* in_sizes, int n_in,
                              void* d_out, int out_size)
{
    (void)in_sizes; (void)n_in; (void)out_size;
    const float* x  = (const float*)d_in[0];
    const float* Wq = (const float*)d_in[1];
    const float* Wk = (const float*)d_in[2];
    const float* Wv = (const float*)d_in[3];
    const float* Wp = (const float*)d_in[4];
    const float* bp = (const float*)d_in[5];
    float* out = (float*)d_out;

    cudaFuncSetAttribute(flash_mma,
                         cudaFuncAttributeMaxDynamicSharedMemorySize,
                         FA_SMEM_BYTES);

    dim3 g_qkv(CEMB / 128, MTOT / 128, 3);   // (8, 64, 3)
    qkv_gemm<<<g_qkv, 256>>>(x, Wq, Wk, Wv);

    dim3 g_fl(TT / 64, BB * NHEAD);          // (32, 64)
    flash_mma<<<g_fl, 128, FA_SMEM_BYTES>>>();

    dim3 g_pr(CEMB / 128, MTOT / 128);       // (8, 64)
    proj_gemm<<<g_pr, 256>>>(Wp, bp, out);
}

// round 4
// speedup vs baseline: 3.3062x; 1.2798x over previous
#include <cuda_runtime.h>
#include <cuda_bf16.h>
#include <math.h>

#define NHEAD 16
#define HS    64
#define CEMB  1024
#define BB    4
#define TT    2048
#define MTOT  (BB*TT)          // 8192
#define KTILE 16
#define LDA   136

// Scratch (module-load allocated; not runtime alloc)
__device__ float g_q[(size_t)BB*NHEAD*TT*HS];
__device__ float g_att[(size_t)MTOT*CEMB];
__device__ __nv_bfloat16 g_khi[(size_t)BB*NHEAD*TT*HS];
__device__ __nv_bfloat16 g_klo[(size_t)BB*NHEAD*TT*HS];
__device__ __nv_bfloat16 g_vthi[(size_t)BB*NHEAD*TT*HS];  // [bh][d][t]
__device__ __nv_bfloat16 g_vtlo[(size_t)BB*NHEAD*TT*HS];

__device__ __forceinline__ float tf32r(float x) {
    unsigned u;
    asm("cvt.rna.tf32.f32 %0, %1;" : "=r"(u) : "f"(x));
    return __uint_as_float(u);
}

__device__ __forceinline__ void mma_tf32(float c[4], const unsigned a[4],
                                         const unsigned b[2]) {
    asm volatile(
        "mma.sync.aligned.m16n8k8.row.col.f32.tf32.tf32.f32 "
        "{%0,%1,%2,%3}, {%4,%5,%6,%7}, {%8,%9}, {%0,%1,%2,%3};\n"
        : "+f"(c[0]), "+f"(c[1]), "+f"(c[2]), "+f"(c[3])
        : "r"(a[0]), "r"(a[1]), "r"(a[2]), "r"(a[3]),
          "r"(b[0]), "r"(b[1]));
}

__device__ __forceinline__ void mma_bf16(float c[4], const unsigned a[4],
                                         unsigned b0, unsigned b1) {
    asm volatile(
        "mma.sync.aligned.m16n8k16.row.col.f32.bf16.bf16.f32 "
        "{%0,%1,%2,%3}, {%4,%5,%6,%7}, {%8,%9}, {%0,%1,%2,%3};\n"
        : "+f"(c[0]), "+f"(c[1]), "+f"(c[2]), "+f"(c[3])
        : "r"(a[0]), "r"(a[1]), "r"(a[2]), "r"(a[3]),
          "r"(b0), "r"(b1));
}

__device__ __forceinline__ unsigned pk(__nv_bfloat16 x, __nv_bfloat16 y) {
    unsigned short a = *(unsigned short*)&x, b = *(unsigned short*)&y;
    return (unsigned)a | ((unsigned)b << 16);
}

// split (a,b) into packed bf16 hi pair and lo pair
__device__ __forceinline__ void split2(float a, float b,
                                       unsigned &hi, unsigned &lo) {
    __nv_bfloat16 ah = __float2bfloat16(a);
    __nv_bfloat16 bh = __float2bfloat16(b);
    __nv_bfloat16 al = __float2bfloat16(a - __bfloat162float(ah));
    __nv_bfloat16 bl = __float2bfloat16(b - __bfloat162float(bh));
    hi = pk(ah, bh);
    lo = pk(al, bl);
}

// ---------------------------------------------------------------------------
// tf32 MMA GEMM 128x128 (validated). mode 0=Q(+RoPE)->fp32, 1=K(+RoPE)->bf16
// hi/lo planes, 2=V->transposed bf16 hi/lo planes.
// ---------------------------------------------------------------------------
__global__ void __launch_bounds__(256) qkv_gemm(
    const float* __restrict__ X,
    const float* __restrict__ Wq,
    const float* __restrict__ Wk,
    const float* __restrict__ Wv)
{
    const int mode = blockIdx.z;
    const float* W = (mode == 0) ? Wq : ((mode == 1) ? Wk : Wv);

    __shared__ float As[KTILE][LDA];
    __shared__ float Bs[KTILE][LDA];

    const int tid  = threadIdx.x;
    const int warp = tid >> 5;
    const int lane = tid & 31;
    const int wm = warp >> 1;
    const int wn = warp & 1;
    const int m0 = blockIdx.y * 128;
    const int n0 = blockIdx.x * 128;

    float acc[2][8][4];
#pragma unroll
    for (int mt = 0; mt < 2; mt++)
#pragma unroll
        for (int nt = 0; nt < 8; nt++)
#pragma unroll
            for (int r = 0; r < 4; r++) acc[mt][nt][r] = 0.0f;

    float4 ra[2], rb[2];
#pragma unroll
    for (int i = 0; i < 2; i++) {
        int s = tid + 256 * i;
        int am = s >> 2, akq = s & 3;
        ra[i] = *(const float4*)(X + (size_t)(m0 + am) * CEMB + akq * 4);
        int bk = s >> 5, bnq = s & 31;
        rb[i] = *(const float4*)(W + (size_t)bk * CEMB + n0 + bnq * 4);
    }

    for (int kb = 0; kb < CEMB; kb += KTILE) {
#pragma unroll
        for (int i = 0; i < 2; i++) {
            int s = tid + 256 * i;
            int am = s >> 2, akq = s & 3;
            As[akq * 4 + 0][am] = tf32r(ra[i].x);
            As[akq * 4 + 1][am] = tf32r(ra[i].y);
            As[akq * 4 + 2][am] = tf32r(ra[i].z);
            As[akq * 4 + 3][am] = tf32r(ra[i].w);
            int bk = s >> 5, bnq = s & 31;
            float4 t = make_float4(tf32r(rb[i].x), tf32r(rb[i].y),
                                   tf32r(rb[i].z), tf32r(rb[i].w));
            *(float4*)&Bs[bk][bnq * 4] = t;
        }
        __syncthreads();

        if (kb + KTILE < CEMB) {
#pragma unroll
            for (int i = 0; i < 2; i++) {
                int s = tid + 256 * i;
                int am = s >> 2, akq = s & 3;
                ra[i] = *(const float4*)(X + (size_t)(m0 + am) * CEMB +
                                         kb + KTILE + akq * 4);
                int bk = s >> 5, bnq = s & 31;
                rb[i] = *(const float4*)(W + (size_t)(kb + KTILE + bk) * CEMB +
                                         n0 + bnq * 4);
            }
        }

#pragma unroll
        for (int ks = 0; ks < KTILE; ks += 8) {
            const int kr = ks + (lane & 3);
            const int mrow = wm * 32 + (lane >> 2);
            const int ncol = wn * 64 + (lane >> 2);
            unsigned af[2][4], bf[8][2];
#pragma unroll
            for (int mt = 0; mt < 2; mt++) {
                af[mt][0] = __float_as_uint(As[kr    ][mrow + mt * 16    ]);
                af[mt][1] = __float_as_uint(As[kr    ][mrow + mt * 16 + 8]);
                af[mt][2] = __float_as_uint(As[kr + 4][mrow + mt * 16    ]);
                af[mt][3] = __float_as_uint(As[kr + 4][mrow + mt * 16 + 8]);
            }
#pragma unroll
            for (int nt = 0; nt < 8; nt++) {
                bf[nt][0] = __float_as_uint(Bs[kr    ][ncol + nt * 8]);
                bf[nt][1] = __float_as_uint(Bs[kr + 4][ncol + nt * 8]);
            }
#pragma unroll
            for (int mt = 0; mt < 2; mt++)
#pragma unroll
                for (int nt = 0; nt < 8; nt++)
                    mma_tf32(acc[mt][nt], af[mt], bf[nt]);
        }
        __syncthreads();
    }

    const float L2T = 13.287712379549449f / 64.0f;  // log2(10000)/64
#pragma unroll
    for (int mt = 0; mt < 2; mt++) {
        const int row_base = m0 + wm * 32 + mt * 16 + (lane >> 2);
#pragma unroll
        for (int nt = 0; nt < 8; nt++) {
            const int col = n0 + wn * 64 + nt * 8 + (lane & 3) * 2;
            const int h = col >> 6;
            const int d = col & 63;
#pragma unroll
            for (int half = 0; half < 2; half++) {
                const int row = row_base + half * 8;
                const int b = row >> 11;
                const int t = row & 2047;
                float x0 = acc[mt][nt][half * 2];
                float x1 = acc[mt][nt][half * 2 + 1];
                float o0 = x0, o1 = x1;
                if (mode < 2) {
                    float inv = exp2f(-(float)d * L2T);
                    float ang = (float)t * inv;
                    float sv, cv;
                    sincosf(ang, &sv, &cv);
                    o0 = x0 * cv - x1 * sv;
                    o1 = x0 * sv + x1 * cv;
                }
                const int bh = b * NHEAD + h;
                if (mode == 0) {
                    size_t base = ((size_t)bh * TT + t) * HS + d;
                    *(float2*)(g_q + base) = make_float2(o0, o1);
                } else if (mode == 1) {
                    size_t base = ((size_t)bh * TT + t) * HS + d;
                    unsigned hi, lo;
                    split2(o0, o1, hi, lo);
                    *(unsigned*)(g_khi + base) = hi;
                    *(unsigned*)(g_klo + base) = lo;
                } else {
                    size_t tb = ((size_t)bh * HS + d) * TT + t;
                    __nv_bfloat16 h0 = __float2bfloat16(o0);
                    __nv_bfloat16 h1 = __float2bfloat16(o1);
                    g_vthi[tb]      = h0;
                    g_vthi[tb + TT] = h1;
                    g_vtlo[tb] =
                        __float2bfloat16(o0 - __bfloat162float(h0));
                    g_vtlo[tb + TT] =
                        __float2bfloat16(o1 - __bfloat162float(h1));
                }
            }
        }
    }
}

// ---------------------------------------------------------------------------
// Flash attention, bf16x3 on tensor pipe. BM=64 (4 warps x m16), BN=64.
// K smem: hi/lo planes [j][d] stride 72; V smem: hi/lo planes [d][j] str 72.
// P stays entirely in registers (C-frag cols == A-frag k-pairs for k16).
// ---------------------------------------------------------------------------
#define KVS 72

__global__ void __launch_bounds__(128) flash_bf16()
{
    __shared__ __nv_bfloat16 KhiS[64][KVS];
    __shared__ __nv_bfloat16 KloS[64][KVS];
    __shared__ __nv_bfloat16 VhiS[64][KVS];   // [d][j]
    __shared__ __nv_bfloat16 VloS[64][KVS];

    const int tid  = threadIdx.x;
    const int warp = tid >> 5;
    const int lane = tid & 31;
    const int qt   = gridDim.x - 1 - blockIdx.x;
    const int q0   = qt * 64;
    const int bh   = blockIdx.y;

    const float* Q = g_q + (size_t)bh * TT * HS;
    const __nv_bfloat16* Khi = g_khi + (size_t)bh * TT * HS;
    const __nv_bfloat16* Klo = g_klo + (size_t)bh * TT * HS;
    const __nv_bfloat16* Vhi = g_vthi + (size_t)bh * HS * TT;
    const __nv_bfloat16* Vlo = g_vtlo + (size_t)bh * HS * TT;

    const int lr = lane >> 2;           // 0..7
    const int lc = lane & 3;            // 0..3
    const int lrow = warp * 16 + lr;    // local row (first of pair)
    const int grow_a = q0 + lrow;
    const int grow_b = grow_a + 8;

    // ---- Q fragments from global, scaled + split (once per block)
    unsigned qh[4][4], ql[4][4];
#pragma unroll
    for (int ks = 0; ks < 4; ks++) {
        const int kd = ks * 16 + lc * 2;
        const float* qa = Q + (size_t)grow_a * HS;
        const float* qb = Q + (size_t)grow_b * HS;
        float2 v0 = *(const float2*)(qa + kd);
        float2 v1 = *(const float2*)(qb + kd);
        float2 v2 = *(const float2*)(qa + kd + 8);
        float2 v3 = *(const float2*)(qb + kd + 8);
        split2(v0.x * 0.125f, v0.y * 0.125f, qh[ks][0], ql[ks][0]);
        split2(v1.x * 0.125f, v1.y * 0.125f, qh[ks][1], ql[ks][1]);
        split2(v2.x * 0.125f, v2.y * 0.125f, qh[ks][2], ql[ks][2]);
        split2(v3.x * 0.125f, v3.y * 0.125f, qh[ks][3], ql[ks][3]);
    }

    float o[8][4];
#pragma unroll
    for (int nt = 0; nt < 8; nt++)
#pragma unroll
        for (int r = 0; r < 4; r++) o[nt][r] = 0.0f;
    float m_a = -1e30f, m_b = -1e30f, l_a = 0.0f, l_b = 0.0f;

    for (int kt = 0; kt <= qt; kt++) {
        const int k0 = kt * 64;
        __syncthreads();
        // ---- stage K (hi/lo) and Vt (hi/lo): 4 planes x 8 uint2/thread
#pragma unroll
        for (int a = 0; a < 8; a++) {
            int s = a * 128 + tid;
            int j = s >> 4, dq = (s & 15) * 4;
            *(uint2*)&KhiS[j][dq] =
                *(const uint2*)(Khi + (size_t)(k0 + j) * HS + dq);
            *(uint2*)&KloS[j][dq] =
                *(const uint2*)(Klo + (size_t)(k0 + j) * HS + dq);
            *(uint2*)&VhiS[j][dq] =
                *(const uint2*)(Vhi + (size_t)j * TT + k0 + dq);
            *(uint2*)&VloS[j][dq] =
                *(const uint2*)(Vlo + (size_t)j * TT + k0 + dq);
        }
        __syncthreads();

        // ---- S = Q K^T (bf16x3)
        float p[8][4];
#pragma unroll
        for (int nt = 0; nt < 8; nt++)
#pragma unroll
            for (int r = 0; r < 4; r++) p[nt][r] = 0.0f;

#pragma unroll
        for (int ks = 0; ks < 4; ks++) {
            const int kd = ks * 16 + lc * 2;
#pragma unroll
            for (int nt = 0; nt < 8; nt++) {
                const int j = nt * 8 + lr;
                unsigned bh0 = *(const unsigned*)&KhiS[j][kd];
                unsigned bh1 = *(const unsigned*)&KhiS[j][kd + 8];
                unsigned bl0 = *(const unsigned*)&KloS[j][kd];
                unsigned bl1 = *(const unsigned*)&KloS[j][kd + 8];
                mma_bf16(p[nt], qh[ks], bh0, bh1);
                mma_bf16(p[nt], qh[ks], bl0, bl1);
                mma_bf16(p[nt], ql[ks], bh0, bh1);
            }
        }

        // ---- causal mask (diagonal tile only)
        if (kt == qt) {
#pragma unroll
            for (int nt = 0; nt < 8; nt++) {
                const int c = k0 + nt * 8 + lc * 2;
                if (c     > grow_a) p[nt][0] = -1e30f;
                if (c + 1 > grow_a) p[nt][1] = -1e30f;
                if (c     > grow_b) p[nt][2] = -1e30f;
                if (c + 1 > grow_b) p[nt][3] = -1e30f;
            }
        }

        // ---- online softmax
        float ma = -1e30f, mb = -1e30f;
#pragma unroll
        for (int nt = 0; nt < 8; nt++) {
            ma = fmaxf(ma, fmaxf(p[nt][0], p[nt][1]));
            mb = fmaxf(mb, fmaxf(p[nt][2], p[nt][3]));
        }
        ma = fmaxf(ma, __shfl_xor_sync(0xffffffffu, ma, 1));
        ma = fmaxf(ma, __shfl_xor_sync(0xffffffffu, ma, 2));
        mb = fmaxf(mb, __shfl_xor_sync(0xffffffffu, mb, 1));
        mb = fmaxf(mb, __shfl_xor_sync(0xffffffffu, mb, 2));

        const float mna = fmaxf(m_a, ma);
        const float mnb = fmaxf(m_b, mb);
        const float ca = __expf(m_a - mna);
        const float cb = __expf(m_b - mnb);

        float sa = 0.0f, sb = 0.0f;
#pragma unroll
        for (int nt = 0; nt < 8; nt++) {
            p[nt][0] = __expf(p[nt][0] - mna);
            p[nt][1] = __expf(p[nt][1] - mna);
            p[nt][2] = __expf(p[nt][2] - mnb);
            p[nt][3] = __expf(p[nt][3] - mnb);
            sa += p[nt][0] + p[nt][1];
            sb += p[nt][2] + p[nt][3];
        }
        sa += __shfl_xor_sync(0xffffffffu, sa, 1);
        sa += __shfl_xor_sync(0xffffffffu, sa, 2);
        sb += __shfl_xor_sync(0xffffffffu, sb, 1);
        sb += __shfl_xor_sync(0xffffffffu, sb, 2);
        l_a = l_a * ca + sa;  m_a = mna;
        l_b = l_b * cb + sb;  m_b = mnb;

#pragma unroll
        for (int nt = 0; nt < 8; nt++) {
            o[nt][0] *= ca; o[nt][1] *= ca;
            o[nt][2] *= cb; o[nt][3] *= cb;
        }

        // ---- P fragments in registers (C-frag cols == A-frag k-pairs)
        unsigned pah[4][4], pal[4][4];
#pragma unroll
        for (int g = 0; g < 4; g++) {
            split2(p[2*g][0],   p[2*g][1],   pah[g][0], pal[g][0]);
            split2(p[2*g][2],   p[2*g][3],   pah[g][1], pal[g][1]);
            split2(p[2*g+1][0], p[2*g+1][1], pah[g][2], pal[g][2]);
            split2(p[2*g+1][2], p[2*g+1][3], pah[g][3], pal[g][3]);
        }

        // ---- O += P V (bf16x3)
#pragma unroll
        for (int g = 0; g < 4; g++) {
            const int j0 = g * 16 + lc * 2;
#pragma unroll
            for (int nt = 0; nt < 8; nt++) {
                const int dcol = nt * 8 + lr;
                unsigned bh0 = *(const unsigned*)&VhiS[dcol][j0];
                unsigned bh1 = *(const unsigned*)&VhiS[dcol][j0 + 8];
                unsigned bl0 = *(const unsigned*)&VloS[dcol][j0];
                unsigned bl1 = *(const unsigned*)&VloS[dcol][j0 + 8];
                mma_bf16(o[nt], pah[g], bh0, bh1);
                mma_bf16(o[nt], pah[g], bl0, bl1);
                mma_bf16(o[nt], pal[g], bh0, bh1);
            }
        }
    }

    // ---- epilogue
    const float rla = 1.0f / l_a;
    const float rlb = 1.0f / l_b;
    const int b = bh >> 4;
    const int h = bh & 15;
    float* oa = g_att + ((size_t)b * TT + grow_a) * CEMB + h * HS;
    float* ob = g_att + ((size_t)b * TT + grow_b) * CEMB + h * HS;
#pragma unroll
    for (int nt = 0; nt < 8; nt++) {
        const int col = nt * 8 + lc * 2;
        *(float2*)(oa + col) = make_float2(o[nt][0] * rla, o[nt][1] * rla);
        *(float2*)(ob + col) = make_float2(o[nt][2] * rlb, o[nt][3] * rlb);
    }
}

// ---------------------------------------------------------------------------
// Output projection (tf32 MMA): g_att [8192,1024] @ Wp + bp -> d_out
// ---------------------------------------------------------------------------
__global__ void __launch_bounds__(256) proj_gemm(
    const float* __restrict__ Wp,
    const float* __restrict__ bp,
    float* __restrict__ out)
{
    __shared__ float As[KTILE][LDA];
    __shared__ float Bs[KTILE][LDA];

    const int tid  = threadIdx.x;
    const int warp = tid >> 5;
    const int lane = tid & 31;
    const int wm = warp >> 1;
    const int wn = warp & 1;
    const int m0 = blockIdx.y * 128;
    const int n0 = blockIdx.x * 128;

    float acc[2][8][4];
#pragma unroll
    for (int mt = 0; mt < 2; mt++)
#pragma unroll
        for (int nt = 0; nt < 8; nt++)
#pragma unroll
            for (int r = 0; r < 4; r++) acc[mt][nt][r] = 0.0f;

    float4 ra[2], rb[2];
#pragma unroll
    for (int i = 0; i < 2; i++) {
        int s = tid + 256 * i;
        int am = s >> 2, akq = s & 3;
        ra[i] = *(const float4*)(g_att + (size_t)(m0 + am) * CEMB + akq * 4);
        int bk = s >> 5, bnq = s & 31;
        rb[i] = *(const float4*)(Wp + (size_t)bk * CEMB + n0 + bnq * 4);
    }

    for (int kb = 0; kb < CEMB; kb += KTILE) {
#pragma unroll
        for (int i = 0; i < 2; i++) {
            int s = tid + 256 * i;
            int am = s >> 2, akq = s & 3;
            As[akq * 4 + 0][am] = tf32r(ra[i].x);
            As[akq * 4 + 1][am] = tf32r(ra[i].y);
            As[akq * 4 + 2][am] = tf32r(ra[i].z);
            As[akq * 4 + 3][am] = tf32r(ra[i].w);
            int bk = s >> 5, bnq = s & 31;
            float4 t = make_float4(tf32r(rb[i].x), tf32r(rb[i].y),
                                   tf32r(rb[i].z), tf32r(rb[i].w));
            *(float4*)&Bs[bk][bnq * 4] = t;
        }
        __syncthreads();

        if (kb + KTILE < CEMB) {
#pragma unroll
            for (int i = 0; i < 2; i++) {
                int s = tid + 256 * i;
                int am = s >> 2, akq = s & 3;
                ra[i] = *(const float4*)(g_att + (size_t)(m0 + am) * CEMB +
                                         kb + KTILE + akq * 4);
                int bk = s >> 5, bnq = s & 31;
                rb[i] = *(const float4*)(Wp + (size_t)(kb + KTILE + bk) * CEMB +
                                         n0 + bnq * 4);
            }
        }

#pragma unroll
        for (int ks = 0; ks < KTILE; ks += 8) {
            const int kr = ks + (lane & 3);
            const int mrow = wm * 32 + (lane >> 2);
            const int ncol = wn * 64 + (lane >> 2);
            unsigned af[2][4], bf[8][2];
#pragma unroll
            for (int mt = 0; mt < 2; mt++) {
                af[mt][0] = __float_as_uint(As[kr    ][mrow + mt * 16    ]);
                af[mt][1] = __float_as_uint(As[kr    ][mrow + mt * 16 + 8]);
                af[mt][2] = __float_as_uint(As[kr + 4][mrow + mt * 16    ]);
                af[mt][3] = __float_as_uint(As[kr + 4][mrow + mt * 16 + 8]);
            }
#pragma unroll
            for (int nt = 0; nt < 8; nt++) {
                bf[nt][0] = __float_as_uint(Bs[kr    ][ncol + nt * 8]);
                bf[nt][1] = __float_as_uint(Bs[kr + 4][ncol + nt * 8]);
            }
#pragma unroll
            for (int mt = 0; mt < 2; mt++)
#pragma unroll
                for (int nt = 0; nt < 8; nt++)
                    mma_tf32(acc[mt][nt], af[mt], bf[nt]);
        }
        __syncthreads();
    }

#pragma unroll
    for (int mt = 0; mt < 2; mt++) {
        const int row_base = m0 + wm * 32 + mt * 16 + (lane >> 2);
#pragma unroll
        for (int nt = 0; nt < 8; nt++) {
            const int col = n0 + wn * 64 + nt * 8 + (lane & 3) * 2;
            const float b0 = bp[col];
            const float b1 = bp[col + 1];
#pragma unroll
            for (int half = 0; half < 2; half++) {
                const int row = row_base + half * 8;
                *(float2*)(out + (size_t)row * CEMB + col) =
                    make_float2(acc[mt][nt][half * 2]     + b0,
                                acc[mt][nt][half * 2 + 1] + b1);
            }
        }
    }
}

// ---------------------------------------------------------------------------
extern "C" void kernel_launch(void* const* d_in, const int* in_sizes, int n_in,
                              void* d_out, int out_size)
{
    (void)in_sizes; (void)n_in; (void)out_size;
    const float* x  = (const float*)d_in[0];
    const float* Wq = (const float*)d_in[1];
    const float* Wk = (const float*)d_in[2];
    const float* Wv = (const float*)d_in[3];
    const float* Wp = (const float*)d_in[4];
    const float* bp = (const float*)d_in[5];
    float* out = (float*)d_out;

    dim3 g_qkv(CEMB / 128, MTOT / 128, 3);   // (8, 64, 3)
    qkv_gemm<<<g_qkv, 256>>>(x, Wq, Wk, Wv);

    dim3 g_fl(TT / 64, BB * NHEAD);          // (32, 64)
    flash_bf16<<<g_fl, 128>>>();

    dim3 g_pr(CEMB / 128, MTOT / 128);       // (8, 64)
    proj_gemm<<<g_pr, 256>>>(Wp, bp, out);
}